// round 6
// baseline (speedup 1.0000x reference)
#include <cuda_runtime.h>
#include <math.h>

#define TT   512
#define BB   64
#define HH   512
#define GG   2048   // 4*HH
#define EE   512
#define NCTA 128
#define UPC  4      // h-units per CTA  (HH / NCTA)
#define RPC  16     // gate rows per CTA (4 * UPC)
#define HB   (HH * BB)

typedef unsigned long long u64;

// ---------------- packed fp32x2 helpers (sm_103a FFMA2) ----------------
__device__ __forceinline__ u64 pack2(float lo, float hi) {
    u64 r; asm("mov.b64 %0,{%1,%2};" : "=l"(r) : "f"(lo), "f"(hi)); return r;
}
__device__ __forceinline__ void ffma2(u64 &d, u64 a, u64 b) {
    asm("fma.rn.f32x2 %0,%1,%2,%0;" : "+l"(d) : "l"(a), "l"(b));
}
__device__ __forceinline__ u64 fadd2(u64 a, u64 b) {
    u64 r; asm("add.rn.f32x2 %0,%1,%2;" : "=l"(r) : "l"(a), "l"(b)); return r;
}

// ---------------- scratch (device globals) ----------------
__device__ float g_x0[(size_t)TT * EE * BB];   // embedded input,  [T][E][B]
__device__ float g_xw[(size_t)TT * GG * BB];   // xW + bias,       [T][G][B]
__device__ float g_y0[(size_t)TT * HH * BB];   // layer0 outputs,  [T][H][B]
__device__ float g_y1[(size_t)TT * HH * BB];   // layer1 outputs,  [T][H][B]
__device__ float g_hbuf[2 * HB];               // double-buffered h, [2][H][B]
__device__ unsigned g_bar;                     // grid barrier counter

// ---------------- grid barrier (128 co-resident CTAs, wrap-safe) ----------------
__device__ __forceinline__ void grid_sync() {
    __syncthreads();
    if (threadIdx.x == 0) {
        __threadfence();
        unsigned ticket = atomicAdd(&g_bar, 1u);
        unsigned target = ticket - (ticket & (NCTA - 1)) + NCTA;
        while ((int)(*(volatile unsigned*)&g_bar - target) < 0) { }
        __threadfence();
    }
    __syncthreads();
}

// ---------------- embedding gather ----------------
__global__ void embed_kernel(const int* __restrict__ src,
                             const float* __restrict__ emb) {
    size_t idx = (size_t)blockIdx.x * blockDim.x + threadIdx.x;
    if (idx >= (size_t)TT * EE * BB) return;
    int b = (int)(idx & 63);
    int e = (int)((idx >> 6) & (EE - 1));
    int t = (int)(idx >> 15);
    g_x0[idx] = emb[(size_t)src[t * BB + b] * EE + e];
}

// ---------------- GEMM: C[t][col][b] = sum_k A[t][k][b]*W[col][k] + bias ----------------
// Block 256 thr = 8 warps. Warp: 16 cols x 64 batches (lane = 2 batches, f32x2).
// W staged in smem as DUPLICATED float2 pairs -> LDS.128 feeds FFMA2 directly (no pack MOVs).
__global__ void __launch_bounds__(256) gemm_xw_kernel(const float* __restrict__ W,
                                                      const float* __restrict__ b1,
                                                      const float* __restrict__ b2,
                                                      int layer) {
    const float* __restrict__ A = layer ? g_y0 : g_x0;
    float* __restrict__ C = g_xw;

    __shared__ float2 sWd[64][128];   // [kk][col] duplicated pairs (64 KB)

    const int tid  = threadIdx.x;
    const int t    = blockIdx.y;
    const int n0   = blockIdx.x * 128;
    const int wid  = tid >> 5;
    const int lane = tid & 31;
    const int c0   = wid * 16;
    const int lcol = tid & 127;       // fill: column
    const int lkh  = tid >> 7;        // fill: k half (0/1)

    u64 acc[16];
    #pragma unroll
    for (int r = 0; r < 16; ++r) acc[r] = 0ull;

    for (int kc = 0; kc < 512; kc += 64) {
        __syncthreads();
        // fill W tile (duplicated): sWd[kk][col] = (w, w)
        const float* wrow = W + (size_t)(n0 + lcol) * 512 + kc + lkh * 32;
        #pragma unroll
        for (int i = 0; i < 8; ++i) {
            float4 w4 = *(const float4*)(wrow + i * 4);
            int kk = lkh * 32 + i * 4;
            sWd[kk + 0][lcol] = make_float2(w4.x, w4.x);
            sWd[kk + 1][lcol] = make_float2(w4.y, w4.y);
            sWd[kk + 2][lcol] = make_float2(w4.z, w4.z);
            sWd[kk + 3][lcol] = make_float2(w4.w, w4.w);
        }
        __syncthreads();

        const u64* ap = (const u64*)(A + ((size_t)t * 512 + kc) * 64) + lane;
        #pragma unroll 4
        for (int kk = 0; kk < 64; ++kk) {
            u64 a = ap[(size_t)kk * 32];
            const ulonglong2* wk = (const ulonglong2*)&sWd[kk][c0];
            #pragma unroll
            for (int p = 0; p < 8; ++p) {
                ulonglong2 w2 = wk[p];          // two duplicated W pairs (LDS.128)
                ffma2(acc[2 * p + 0], a, w2.x);
                ffma2(acc[2 * p + 1], a, w2.y);
            }
        }
    }

    #pragma unroll
    for (int r = 0; r < 16; ++r) {
        int col = n0 + c0 + r;
        float bias = b1[col] + b2[col];
        u64 v = fadd2(acc[r], pack2(bias, bias));
        *((u64*)(C + ((size_t)t * GG + col) * BB) + lane) = v;
    }
}

// ---------------- persistent LSTM recurrence ----------------
// 128 CTAs x 256 threads. CTA owns 16 gate rows (4 h-units).
// Warp = k-slice of 64 (8 warps); lane = 2 batches (f32x2); all 16 rows per warp.
// Whh stored in smem as DUPLICATED float2 pairs [k][row]; h read directly from gmem (L2).
__global__ void __launch_bounds__(256, 1) lstm_rec_kernel(const float* __restrict__ Whh,
                                                          int layer) {
    extern __shared__ float smem[];
    float2* sWd = (float2*)smem;              // [512][16] dup pairs = 64 KB
    float*  sP  = smem + 512 * 16 * 2;        // [8][16][64] = 32 KB
    float*  sC  = sP + 8 * 16 * 64;           // [4][64]

    const float* __restrict__ xw = g_xw;
    float* __restrict__ y = layer ? g_y1 : g_y0;
    float* hbuf = g_hbuf;

    const int tid = threadIdx.x;
    const int cta = blockIdx.x;
    const int u0  = cta * UPC;

    // Load Whh slice duplicated+transposed: sWd[k][r]=(w,w); row r=q*4+j <-> global q*HH+u0+j
    {
        const int r = tid >> 4;            // 16 rows, 16 threads each
        const int q = r >> 2, j = r & 3;
        const float* srcw = Whh + (size_t)(q * HH + u0 + j) * HH;
        #pragma unroll
        for (int c = 0; c < 8; ++c) {
            int k = c * 64 + (tid & 15) * 4;
            float4 w = *(const float4*)(srcw + k);
            sWd[(k + 0) * 16 + r] = make_float2(w.x, w.x);
            sWd[(k + 1) * 16 + r] = make_float2(w.y, w.y);
            sWd[(k + 2) * 16 + r] = make_float2(w.z, w.z);
            sWd[(k + 3) * 16 + r] = make_float2(w.w, w.w);
        }
    }
    for (int i = tid; i < UPC * BB; i += 256) sC[i] = 0.f;
    for (int i = tid; i < UPC * BB; i += 256) hbuf[u0 * BB + i] = 0.f;
    grid_sync();

    const int ksl  = tid >> 5;     // warp = k-slice
    const int lane = tid & 31;
    const int bb = tid & 63, jj = tid >> 6;   // gate-phase mapping

    int cur = 0;
    for (int t = 0; t < TT; ++t) {
        // ---- dot: acc[r] += h[k][2b..2b+1] * W[r][k] over this warp's 64-k slice ----
        u64 acc[16];
        #pragma unroll
        for (int r = 0; r < 16; ++r) acc[r] = 0ull;

        const u64* hp = (const u64*)(hbuf + cur * HB + ksl * 64 * BB) + lane;
        const ulonglong2* wp = (const ulonglong2*)(sWd + (size_t)(ksl * 64) * 16);
        #pragma unroll 4
        for (int kk = 0; kk < 64; ++kk) {
            u64 h2 = __ldcg(hp + (size_t)kk * 32);
            // one k-row = 16 dup pairs = 128 B = 8 ulonglong2  (stride fixed: kk*8)
            const ulonglong2* wk = wp + kk * 8;
            #pragma unroll
            for (int p = 0; p < 8; ++p) {
                ulonglong2 w2 = wk[p];
                ffma2(acc[2 * p + 0], h2, w2.x);
                ffma2(acc[2 * p + 1], h2, w2.y);
            }
        }
        // store partials: sP[ksl][r][lane*2..+1]
        {
            u64* pp = (u64*)(sP + (ksl * 16) * 64) + lane;
            #pragma unroll
            for (int r = 0; r < 16; ++r) pp[r * 32] = acc[r];
        }
        __syncthreads();

        // ---- gates: thread = (jj unit, bb batch) ----
        {
            float gv4[4];
            #pragma unroll
            for (int q = 0; q < 4; ++q) {
                int col = q * HH + u0 + jj;
                int r   = q * 4 + jj;
                float v = __ldg(xw + ((size_t)t * GG + col) * BB + bb);
                #pragma unroll
                for (int s = 0; s < 8; ++s)
                    v += sP[(s * 16 + r) * 64 + bb];
                gv4[q] = v;
            }
            float iv = 1.f / (1.f + __expf(-gv4[0]));
            float fv = 1.f / (1.f + __expf(-gv4[1]));
            float gv = tanhf(gv4[2]);
            float ov = 1.f / (1.f + __expf(-gv4[3]));
            float c = fv * sC[jj * BB + bb] + iv * gv;
            sC[jj * BB + bb] = c;
            float h = ov * tanhf(c);
            hbuf[(cur ^ 1) * HB + (u0 + jj) * BB + bb] = h;
            y[((size_t)t * HH + (u0 + jj)) * BB + bb] = h;
        }
        grid_sync();
        cur ^= 1;
    }
}

// ---------------- output gather ----------------
__global__ void out_kernel(const int* __restrict__ sen_len, float* __restrict__ out) {
    int idx = blockIdx.x * blockDim.x + threadIdx.x;
    if (idx >= BB * HH) return;
    int b = idx >> 9;
    int u = idx & (HH - 1);
    int t = sen_len[b] - 1;
    out[idx] = g_y1[((size_t)t * HH + u) * BB + b];
}

// ---------------- launch ----------------
static const int REC_SMEM = (512 * 16 * 2 + 8 * 16 * 64 + UPC * BB) * (int)sizeof(float); // 99328

extern "C" void kernel_launch(void* const* d_in, const int* in_sizes, int n_in,
                              void* d_out, int out_size) {
    const int*   src     = (const int*)d_in[0];
    const int*   sen_len = (const int*)d_in[1];
    const float* emb     = (const float*)d_in[2];
    const float* Wih0    = (const float*)d_in[3];
    const float* Whh0    = (const float*)d_in[4];
    const float* bih0    = (const float*)d_in[5];
    const float* bhh0    = (const float*)d_in[6];
    const float* Wih1    = (const float*)d_in[7];
    const float* Whh1    = (const float*)d_in[8];
    const float* bih1    = (const float*)d_in[9];
    const float* bhh1    = (const float*)d_in[10];
    float* out = (float*)d_out;

    cudaFuncSetAttribute(lstm_rec_kernel,
                         cudaFuncAttributeMaxDynamicSharedMemorySize, REC_SMEM);

    embed_kernel<<<(TT * EE * BB + 255) / 256, 256>>>(src, emb);

    dim3 ggrid(GG / 128, TT);
    gemm_xw_kernel<<<ggrid, 256>>>(Wih0, bih0, bhh0, 0);
    lstm_rec_kernel<<<NCTA, 256, REC_SMEM>>>(Whh0, 0);

    gemm_xw_kernel<<<ggrid, 256>>>(Wih1, bih1, bhh1, 1);
    lstm_rec_kernel<<<NCTA, 256, REC_SMEM>>>(Whh1, 1);

    out_kernel<<<(BB * HH + 255) / 256, 256>>>(sen_len, out);
}

// round 9
// speedup vs baseline: 1.1337x; 1.1337x over previous
#include <cuda_runtime.h>
#include <math.h>

#define TT   512
#define BB   64
#define HH   512
#define GG   2048   // 4*HH
#define EE   512
#define NCTA 128
#define HB   (HH * BB)

typedef unsigned long long u64;

// ---------------- packed fp32x2 helpers (sm_103a FFMA2) ----------------
__device__ __forceinline__ u64 pack2(float lo, float hi) {
    u64 r; asm("mov.b64 %0,{%1,%2};" : "=l"(r) : "f"(lo), "f"(hi)); return r;
}
__device__ __forceinline__ void ffma2(u64 &d, u64 a, u64 b) {
    asm("fma.rn.f32x2 %0,%1,%2,%0;" : "+l"(d) : "l"(a), "l"(b));
}
__device__ __forceinline__ u64 fadd2(u64 a, u64 b) {
    u64 r; asm("add.rn.f32x2 %0,%1,%2;" : "=l"(r) : "l"(a), "l"(b)); return r;
}
__device__ __forceinline__ float2 unpack2(u64 v) {
    float2 f; asm("mov.b64 {%0,%1},%2;" : "=f"(f.x), "=f"(f.y) : "l"(v)); return f;
}

// ---------------- scratch (device globals) ----------------
__device__ float  g_x0[(size_t)TT * EE * BB];   // embedded input,  [T][E][B]
__device__ float  g_xw[(size_t)TT * GG * BB];   // xW + bias,       [T][G][B]
__device__ float  g_y0[(size_t)TT * HH * BB];   // layer0 outputs,  [T][H][B]
__device__ float  g_y1[(size_t)TT * HH * BB];   // layer1 outputs,  [T][H][B]
__device__ float2 g_hd[2 * HH * BB];            // dup-paired h, [2][H][B] of (h,h)
__device__ unsigned g_bar;                      // grid barrier counter

// ---------------- grid barrier (128 co-resident CTAs, wrap-safe) ----------------
__device__ __forceinline__ void grid_sync() {
    __syncthreads();
    if (threadIdx.x == 0) {
        __threadfence();
        unsigned ticket = atomicAdd(&g_bar, 1u);
        unsigned target = ticket - (ticket & (NCTA - 1)) + NCTA;
        while ((int)(*(volatile unsigned*)&g_bar - target) < 0) { }
        __threadfence();
    }
    __syncthreads();
}

// ---------------- embedding gather ----------------
__global__ void embed_kernel(const int* __restrict__ src,
                             const float* __restrict__ emb) {
    size_t idx = (size_t)blockIdx.x * blockDim.x + threadIdx.x;
    if (idx >= (size_t)TT * EE * BB) return;
    int b = (int)(idx & 63);
    int e = (int)((idx >> 6) & (EE - 1));
    int t = (int)(idx >> 15);
    g_x0[idx] = emb[(size_t)src[t * BB + b] * EE + e];
}

// ---------------- GEMM: C[t][col][b] = sum_k A[t][k][b]*W[col][k] + bias ----------------
// CTA: 64 batches x 128 cols, 256 thr, 8 warps (warp = 32b x 32c).
// f32x2 lanes span COL PAIRS (W pairs natural from smem); A staged DUP in smem.
// Per warp-kk: 4 LDS.128 (W) + 1 LDS.128 (A dup) + 16 FFMA2, zero pack MOVs.
__global__ void __launch_bounds__(256) gemm_xw_kernel(const float* __restrict__ W,
                                                      const float* __restrict__ b1,
                                                      const float* __restrict__ b2,
                                                      int layer) {
    const float* __restrict__ A = layer ? g_y0 : g_x0;
    float* __restrict__ C = g_xw;

    extern __shared__ float2 sm[];
    float2* sA  = sm;              // [64 kk][64 b] dup pairs (32 KB)
    float2* sWp = sm + 64 * 64;    // [64 kk][64 colpairs]    (32 KB)

    const int tid  = threadIdx.x;
    const int t    = blockIdx.y;
    const int n0   = blockIdx.x * 128;
    const int wid  = tid >> 5;
    const int lane = tid & 31;
    const int bhh  = wid & 1;            // batch half
    const int cq   = wid >> 1;           // col quarter
    const int bp   = lane & 15;          // batch pair
    const int ch   = lane >> 4;          // col half within quarter
    const int cp0  = cq * 16 + ch * 8;   // first colpair (8 per thread)
    // fill mappings
    const int fa_k = tid >> 2, fa_b = (tid & 3) * 16;      // A fill
    const int fw_c = tid & 63, fw_k = (tid >> 6) * 16;     // W fill

    u64 acc0[8], acc1[8];
    #pragma unroll
    for (int i = 0; i < 8; ++i) { acc0[i] = 0ull; acc1[i] = 0ull; }

    for (int kc = 0; kc < 512; kc += 64) {
        __syncthreads();
        // --- A tile, duplicated: sA[kk][b] = (a, a) ---
        {
            const float4* ar = (const float4*)(A + ((size_t)t * 512 + kc + fa_k) * 64 + fa_b);
            ulonglong2* dst = (ulonglong2*)(sA + fa_k * 64 + fa_b);
            #pragma unroll
            for (int i = 0; i < 4; ++i) {
                float4 v = ar[i];
                dst[2 * i + 0] = make_ulonglong2(pack2(v.x, v.x), pack2(v.y, v.y));
                dst[2 * i + 1] = make_ulonglong2(pack2(v.z, v.z), pack2(v.w, v.w));
            }
        }
        // --- W tile, col pairs: sWp[kk][cp] = (W[2cp][k], W[2cp+1][k]) ---
        {
            const float4* w0r = (const float4*)(W + (size_t)(n0 + 2 * fw_c) * 512 + kc + fw_k);
            const float4* w1r = (const float4*)(W + (size_t)(n0 + 2 * fw_c + 1) * 512 + kc + fw_k);
            #pragma unroll
            for (int i = 0; i < 4; ++i) {
                float4 we = w0r[i];
                float4 wo = w1r[i];
                sWp[(fw_k + 4 * i + 0) * 64 + fw_c] = make_float2(we.x, wo.x);
                sWp[(fw_k + 4 * i + 1) * 64 + fw_c] = make_float2(we.y, wo.y);
                sWp[(fw_k + 4 * i + 2) * 64 + fw_c] = make_float2(we.z, wo.z);
                sWp[(fw_k + 4 * i + 3) * 64 + fw_c] = make_float2(we.w, wo.w);
            }
        }
        __syncthreads();

        const ulonglong2* ap = (const ulonglong2*)sA + bhh * 16 + bp;
        const ulonglong2* wq = (const ulonglong2*)sWp + (cp0 >> 1);
        #pragma unroll 8
        for (int kk = 0; kk < 64; ++kk) {
            ulonglong2 ad = ap[kk * 32];          // (a_b0 dup, a_b1 dup)
            ulonglong2 wA = wq[kk * 32 + 0];      // colpairs cp0, cp0+1
            ulonglong2 wB = wq[kk * 32 + 1];
            ulonglong2 wC = wq[kk * 32 + 2];
            ulonglong2 wD = wq[kk * 32 + 3];
            ffma2(acc0[0], wA.x, ad.x); ffma2(acc1[0], wA.x, ad.y);
            ffma2(acc0[1], wA.y, ad.x); ffma2(acc1[1], wA.y, ad.y);
            ffma2(acc0[2], wB.x, ad.x); ffma2(acc1[2], wB.x, ad.y);
            ffma2(acc0[3], wB.y, ad.x); ffma2(acc1[3], wB.y, ad.y);
            ffma2(acc0[4], wC.x, ad.x); ffma2(acc1[4], wC.x, ad.y);
            ffma2(acc0[5], wC.y, ad.x); ffma2(acc1[5], wC.y, ad.y);
            ffma2(acc0[6], wD.x, ad.x); ffma2(acc1[6], wD.x, ad.y);
            ffma2(acc0[7], wD.y, ad.x); ffma2(acc1[7], wD.y, ad.y);
        }
    }

    // epilogue: acc0[i] = (col_e, col_o) for batch b0; acc1[i] for b1
    #pragma unroll
    for (int i = 0; i < 8; ++i) {
        int cp  = cp0 + i;
        int col = n0 + 2 * cp;
        float2 x1 = ((const float2*)b1)[(n0 >> 1) + cp];
        float2 x2 = ((const float2*)b2)[(n0 >> 1) + cp];
        u64 bia = pack2(x1.x + x2.x, x1.y + x2.y);
        float2 f0 = unpack2(fadd2(acc0[i], bia));
        float2 f1 = unpack2(fadd2(acc1[i], bia));
        size_t base = ((size_t)t * GG + col) * BB + bhh * 32 + bp * 2;
        *(u64*)(C + base)      = pack2(f0.x, f1.x);   // col even, batches b0,b1
        *(u64*)(C + base + BB) = pack2(f0.y, f1.y);   // col odd
    }
}

// ---------------- persistent LSTM recurrence ----------------
// 128 CTAs x 256 thr. CTA = (rowset: 32 gate rows = 8 h-units) x (batch half: 32).
// Warp = 64-k slice; lane = (batch pair, row half). f32x2 spans ROW PAIRS
// (W pairs natural from smem); h read dup-paired from global g_hd (written dup
// in the gate phase) -> zero pack MOVs, zero per-step smem staging.
__global__ void __launch_bounds__(256, 1) lstm_rec_kernel(const float* __restrict__ Whh,
                                                          int layer) {
    extern __shared__ float smemf[];
    float2*     sWp = (float2*)smemf;              // [512 k][16 rowpairs] (64 KB)
    ulonglong2* sP  = (ulonglong2*)(sWp + 512 * 16); // [8 ks][16 rp][16 bp] (32 KB)
    float*      sC  = (float*)(sP + 8 * 16 * 16);  // [8 units][32 b] (1 KB)

    const float* __restrict__ xw = g_xw;
    float* __restrict__ y = layer ? g_y1 : g_y0;

    const int tid = threadIdx.x;
    const int rowset = blockIdx.x >> 1;
    const int bh     = blockIdx.x & 1;
    const int u0     = rowset * 8;

    // --- W fill: sWp[k][rp] = (Whh[row_e][k], Whh[row_o][k]), rp = q*4+jp ---
    {
        const int rp = tid & 15;               // q = rp>>2, jp = rp&3
        const int kq = tid >> 4;               // 16 groups x 32 k
        const int q = rp >> 2, jp = rp & 3;
        const float* re = Whh + (size_t)(q * 512 + u0 + 2 * jp) * 512;
        const float* ro = re + 512;
        #pragma unroll
        for (int i = 0; i < 8; ++i) {
            int k = kq * 32 + i * 4;
            float4 we = *(const float4*)(re + k);
            float4 wo = *(const float4*)(ro + k);
            sWp[(k + 0) * 16 + rp] = make_float2(we.x, wo.x);
            sWp[(k + 1) * 16 + rp] = make_float2(we.y, wo.y);
            sWp[(k + 2) * 16 + rp] = make_float2(we.z, wo.z);
            sWp[(k + 3) * 16 + rp] = make_float2(we.w, wo.w);
        }
    }
    // init c and h0 (each CTA owns units u0..u0+7 x its batch half)
    {
        const int jj = tid >> 5, bb = tid & 31;
        sC[jj * 32 + bb] = 0.f;
        g_hd[(size_t)(u0 + jj) * 64 + bh * 32 + bb] = make_float2(0.f, 0.f);
    }
    grid_sync();

    const int ks   = tid >> 5;       // warp = k-slice of 64
    const int lane = tid & 31;
    const int bp   = lane & 15;      // batch pair within half
    const int rh   = lane >> 4;      // row half (rowpairs rh*8 .. rh*8+7)
    const int jj = tid >> 5, bb = tid & 31;   // gate phase mapping

    int cur = 0;
    for (int t = 0; t < TT; ++t) {
        // ---- dot over this warp's 64-k slice ----
        u64 a0[8], a1[8];
        #pragma unroll
        for (int i = 0; i < 8; ++i) { a0[i] = 0ull; a1[i] = 0ull; }

        const ulonglong2* hp =
            (const ulonglong2*)g_hd + (size_t)(cur * 512 + ks * 64) * 32 + bh * 16 + bp;
        const ulonglong2* wq =
            (const ulonglong2*)sWp + (size_t)(ks * 64) * 8 + rh * 4;
        #pragma unroll 8
        for (int kk = 0; kk < 64; ++kk) {
            ulonglong2 hd = __ldcg(hp + (size_t)kk * 32);  // (h_b0 dup, h_b1 dup)
            ulonglong2 w01 = wq[kk * 8 + 0];               // rowpairs rh*8+0,1
            ulonglong2 w23 = wq[kk * 8 + 1];
            ulonglong2 w45 = wq[kk * 8 + 2];
            ulonglong2 w67 = wq[kk * 8 + 3];
            ffma2(a0[0], w01.x, hd.x); ffma2(a1[0], w01.x, hd.y);
            ffma2(a0[1], w01.y, hd.x); ffma2(a1[1], w01.y, hd.y);
            ffma2(a0[2], w23.x, hd.x); ffma2(a1[2], w23.x, hd.y);
            ffma2(a0[3], w23.y, hd.x); ffma2(a1[3], w23.y, hd.y);
            ffma2(a0[4], w45.x, hd.x); ffma2(a1[4], w45.x, hd.y);
            ffma2(a0[5], w45.y, hd.x); ffma2(a1[5], w45.y, hd.y);
            ffma2(a0[6], w67.x, hd.x); ffma2(a1[6], w67.x, hd.y);
            ffma2(a0[7], w67.y, hd.x); ffma2(a1[7], w67.y, hd.y);
        }
        // partials: sP[ks][rp][bp] = (u64 batch-even, u64 batch-odd),
        // each u64 = (row_even, row_odd) f32x2. rp = rh*8 + i.
        {
            ulonglong2* pp = sP + ((size_t)(ks * 16 + rh * 8) * 16 + bp);
            #pragma unroll
            for (int i = 0; i < 8; ++i)
                pp[(size_t)i * 16] = make_ulonglong2(a0[i], a1[i]);
        }
        __syncthreads();

        // ---- gates: thread = (jj unit 0..7, bb batch 0..31) ----
        {
            const float* pf = (const float*)sP;   // [ks][rp][bp][4 floats]
            float gv4[4];
            #pragma unroll
            for (int q = 0; q < 4; ++q) {
                int col = q * 512 + u0 + jj;
                int rp  = q * 4 + (jj >> 1);
                int hf  = jj & 1;
                float v = __ldg(xw + ((size_t)t * GG + col) * BB + bh * 32 + bb);
                #pragma unroll
                for (int s = 0; s < 8; ++s)
                    v += pf[(((s * 16) + rp) * 16 + (bb >> 1)) * 4 + (bb & 1) * 2 + hf];
                gv4[q] = v;
            }
            float iv = 1.f / (1.f + __expf(-gv4[0]));
            float fv = 1.f / (1.f + __expf(-gv4[1]));
            float gv = tanhf(gv4[2]);
            float ov = 1.f / (1.f + __expf(-gv4[3]));
            float c = fv * sC[jj * 32 + bb] + iv * gv;
            sC[jj * 32 + bb] = c;
            float h = ov * tanhf(c);
            g_hd[(size_t)((cur ^ 1) * 512 + u0 + jj) * 64 + bh * 32 + bb] = make_float2(h, h);
            y[((size_t)t * HH + u0 + jj) * BB + bh * 32 + bb] = h;
        }
        grid_sync();
        cur ^= 1;
    }
}

// ---------------- output gather ----------------
__global__ void out_kernel(const int* __restrict__ sen_len, float* __restrict__ out) {
    int idx = blockIdx.x * blockDim.x + threadIdx.x;
    if (idx >= BB * HH) return;
    int b = idx >> 9;
    int u = idx & (HH - 1);
    int t = sen_len[b] - 1;
    out[idx] = g_y1[((size_t)t * HH + u) * BB + b];
}

// ---------------- launch ----------------
static const int GEMM_SMEM = (64 * 64 + 64 * 64) * (int)sizeof(float2);           // 65536
static const int REC_SMEM  = 512 * 16 * 8 + 8 * 16 * 16 * 16 + 8 * 32 * 4;        // 99328

extern "C" void kernel_launch(void* const* d_in, const int* in_sizes, int n_in,
                              void* d_out, int out_size) {
    const int*   src     = (const int*)d_in[0];
    const int*   sen_len = (const int*)d_in[1];
    const float* emb     = (const float*)d_in[2];
    const float* Wih0    = (const float*)d_in[3];
    const float* Whh0    = (const float*)d_in[4];
    const float* bih0    = (const float*)d_in[5];
    const float* bhh0    = (const float*)d_in[6];
    const float* Wih1    = (const float*)d_in[7];
    const float* Whh1    = (const float*)d_in[8];
    const float* bih1    = (const float*)d_in[9];
    const float* bhh1    = (const float*)d_in[10];
    float* out = (float*)d_out;

    cudaFuncSetAttribute(gemm_xw_kernel,
                         cudaFuncAttributeMaxDynamicSharedMemorySize, GEMM_SMEM);
    cudaFuncSetAttribute(lstm_rec_kernel,
                         cudaFuncAttributeMaxDynamicSharedMemorySize, REC_SMEM);

    embed_kernel<<<(TT * EE * BB + 255) / 256, 256>>>(src, emb);

    dim3 ggrid(GG / 128, TT);
    gemm_xw_kernel<<<ggrid, 256, GEMM_SMEM>>>(Wih0, bih0, bhh0, 0);
    lstm_rec_kernel<<<NCTA, 256, REC_SMEM>>>(Whh0, 0);

    gemm_xw_kernel<<<ggrid, 256, GEMM_SMEM>>>(Wih1, bih1, bhh1, 1);
    lstm_rec_kernel<<<NCTA, 256, REC_SMEM>>>(Whh1, 1);

    out_kernel<<<(BB * HH + 255) / 256, 256>>>(sen_len, out);
}

// round 10
// speedup vs baseline: 1.5773x; 1.3912x over previous
#include <cuda_runtime.h>
#include <math.h>

#define TT   512
#define BB   64
#define HH   512
#define GG   2048   // 4*HH
#define EE   512
#define NCTA 128

typedef unsigned long long u64;

// ---------------- packed fp32x2 helpers (sm_103a FFMA2) ----------------
__device__ __forceinline__ u64 pack2(float lo, float hi) {
    u64 r; asm("mov.b64 %0,{%1,%2};" : "=l"(r) : "f"(lo), "f"(hi)); return r;
}
__device__ __forceinline__ void ffma2(u64 &d, u64 a, u64 b) {
    asm("fma.rn.f32x2 %0,%1,%2,%0;" : "+l"(d) : "l"(a), "l"(b));
}
__device__ __forceinline__ float2 unpack2(u64 v) {
    float2 f; asm("mov.b64 {%0,%1},%2;" : "=f"(f.x), "=f"(f.y) : "l"(v)); return f;
}

// ---------------- scratch (device globals) ----------------
__device__ float g_x0[(size_t)TT * EE * BB];     // embedded input,  [T][E][B]
__device__ float g_xw[(size_t)TT * GG * BB];     // x@Wih0 + bias0,  [T][G][B]
__device__ float g_y1[(size_t)TT * HH * BB];     // layer1 outputs,  [T][H][B]
__device__ float g_hall[2 * 1024 * BB];          // [2 buf][h0:0-511 | h1:512-1023][B]
__device__ unsigned g_bar;                       // grid barrier counter

// ---------------- grid barrier (128 co-resident CTAs, wrap-safe) ----------------
__device__ __forceinline__ void grid_sync() {
    __syncthreads();
    if (threadIdx.x == 0) {
        __threadfence();
        unsigned ticket = atomicAdd(&g_bar, 1u);
        unsigned target = ticket - (ticket & (NCTA - 1)) + NCTA;
        while ((int)(*(volatile unsigned*)&g_bar - target) < 0) { }
        __threadfence();
    }
    __syncthreads();
}

// ---------------- embedding gather ----------------
__global__ void embed_kernel(const int* __restrict__ src,
                             const float* __restrict__ emb) {
    size_t idx = (size_t)blockIdx.x * blockDim.x + threadIdx.x;
    if (idx >= (size_t)TT * EE * BB) return;
    int b = (int)(idx & 63);
    int e = (int)((idx >> 6) & (EE - 1));
    int t = (int)(idx >> 15);
    g_x0[idx] = emb[(size_t)src[t * BB + b] * EE + e];
}

// ---------------- GEMM (R3 version, measured best): layer-0 xW only ----------------
// C[t][col][b] = sum_k x0[t][k][b]*Wih0[col][k] + bias
__global__ void __launch_bounds__(128) gemm_xw_kernel(const float* __restrict__ W,
                                                      const float* __restrict__ b1,
                                                      const float* __restrict__ b2) {
    const float* __restrict__ A = g_x0;
    float* __restrict__ C = g_xw;

    __shared__ float As[16][64];     // [k][b]
    __shared__ float Ws[16][132];    // [k][col], padded

    const int tid = threadIdx.x;
    const int t   = blockIdx.y;
    const int n0  = blockIdx.x * 128;
    const int bx  = tid & 7;            // batch group (8 batches)
    const int cy  = tid >> 3;           // col group (8 cols), 0..15
    const int b0  = bx * 8;
    const int c0  = cy * 8;
    const int lw_c = tid >> 2;          // 0..31 (W-load col within chunk)
    const int lw_q = tid & 3;           // 0..3  (W-load k quad)

    u64 acc[8][4];                      // [col][batch-pair]
    #pragma unroll
    for (int j = 0; j < 8; ++j)
        #pragma unroll
        for (int p = 0; p < 4; ++p) acc[j][p] = 0ull;

    for (int k0 = 0; k0 < 512; k0 += 16) {
        // A tile (already [k][b]): 2 float4 per thread
        #pragma unroll
        for (int u = 0; u < 2; ++u) {
            int f  = tid * 2 + u;
            int kk = f >> 4, bb4 = (f & 15) * 4;
            *(float4*)&As[kk][bb4] =
                *(const float4*)(A + ((size_t)t * 512 + k0 + kk) * 64 + bb4);
        }
        // W tile: transpose [col][k] -> [k][col]
        #pragma unroll
        for (int cb = 0; cb < 4; ++cb) {
            int c = cb * 32 + lw_c;
            float4 w = *(const float4*)(W + (size_t)(n0 + c) * 512 + k0 + lw_q * 4);
            Ws[lw_q * 4 + 0][c] = w.x;
            Ws[lw_q * 4 + 1][c] = w.y;
            Ws[lw_q * 4 + 2][c] = w.z;
            Ws[lw_q * 4 + 3][c] = w.w;
        }
        __syncthreads();

        #pragma unroll
        for (int kk = 0; kk < 16; ++kk) {
            ulonglong2 a01 = *(const ulonglong2*)&As[kk][b0];      // b0..b0+3
            ulonglong2 a23 = *(const ulonglong2*)&As[kk][b0 + 4];  // b0+4..b0+7
            float4 wA = *(const float4*)&Ws[kk][c0];
            float4 wB = *(const float4*)&Ws[kk][c0 + 4];
            float wv[8] = {wA.x, wA.y, wA.z, wA.w, wB.x, wB.y, wB.z, wB.w};
            #pragma unroll
            for (int j = 0; j < 8; ++j) {
                u64 wp = pack2(wv[j], wv[j]);
                ffma2(acc[j][0], a01.x, wp);
                ffma2(acc[j][1], a01.y, wp);
                ffma2(acc[j][2], a23.x, wp);
                ffma2(acc[j][3], a23.y, wp);
            }
        }
        __syncthreads();
    }

    #pragma unroll
    for (int j = 0; j < 8; ++j) {
        int col = n0 + c0 + j;
        float bias = b1[col] + b2[col];
        float2 p0 = unpack2(acc[j][0]);
        float2 p1 = unpack2(acc[j][1]);
        float2 p2 = unpack2(acc[j][2]);
        float2 p3 = unpack2(acc[j][3]);
        float4 v0 = make_float4(p0.x + bias, p0.y + bias, p1.x + bias, p1.y + bias);
        float4 v1 = make_float4(p2.x + bias, p2.y + bias, p3.x + bias, p3.y + bias);
        float* cp = C + ((size_t)t * GG + col) * BB + b0;
        *(float4*)cp       = v0;
        *(float4*)(cp + 4) = v1;
    }
}

// ---------------- fused 2-layer persistent LSTM recurrence ----------------
// 128 CTAs x 256 thr. CTA owns 4 h-units of EACH layer (16 gate rows per layer),
// full batch 64. Software pipeline: step s runs layer0 @ t=s and layer1 @ t=s-1.
// Layer1 input = [y0[s-1](=h0); h1[s-1]] with fused weight [Wih1|Whh1] (K=1024).
// Dot: warp = k-slice; lane = batch pair; f32x2 over ROW PAIRS (W float2 natural
// from smem, 4 broadcast LDS.128/kk); h plain from L2 (batch pair native), 4 dup
// MOVs/kk. One __syncthreads + one grid barrier per step.
__global__ void __launch_bounds__(256, 1) lstm_fused_kernel(
        const float* __restrict__ Whh0,
        const float* __restrict__ Wih1,
        const float* __restrict__ Whh1,
        const float* __restrict__ bih1,
        const float* __restrict__ bhh1) {
    extern __shared__ float smem[];
    float2* sWp0 = (float2*)smem;                 // [512 k][8 rp]  (32 KB)
    float2* sWp1 = sWp0 + 512 * 8;                // [1024 k][8 rp] (64 KB)
    u64*    sPA  = (u64*)(sWp1 + 1024 * 8);       // [8 ks][8 rp][64 b] (32 KB)
    u64*    sPB  = sPA + 8 * 8 * 64;              // same (32 KB)
    float*  sC0  = (float*)(sPB + 8 * 8 * 64);    // [4][64]
    float*  sC1  = sC0 + 256;                     // [4][64]
    float*  sB1  = sC1 + 256;                     // [16]

    const int tid = threadIdx.x;
    const int cta = blockIdx.x;
    const int u0  = cta * 4;

    // ---- weight fills: sWp[k][rp] = (W[row_e][k], W[row_o][k]), rp = q*2+jh ----
    {
        const int rp = tid >> 5;              // 0..7
        const int ln = tid & 31;
        const int q = rp >> 1, jh = rp & 1;
        const int re = q * 512 + u0 + 2 * jh; // row_e; row_o = re+1
        const float* we0 = Whh0 + (size_t)re * 512;
        const float* wo0 = we0 + 512;
        const float* we1 = Wih1 + (size_t)re * 512;
        const float* wo1 = we1 + 512;
        const float* we2 = Whh1 + (size_t)re * 512;
        const float* wo2 = we2 + 512;
        #pragma unroll
        for (int i = 0; i < 4; ++i) {
            int k = ln * 16 + i * 4;
            float4 ae = *(const float4*)(we0 + k);
            float4 ao = *(const float4*)(wo0 + k);
            sWp0[(k + 0) * 8 + rp] = make_float2(ae.x, ao.x);
            sWp0[(k + 1) * 8 + rp] = make_float2(ae.y, ao.y);
            sWp0[(k + 2) * 8 + rp] = make_float2(ae.z, ao.z);
            sWp0[(k + 3) * 8 + rp] = make_float2(ae.w, ao.w);
            float4 be = *(const float4*)(we1 + k);
            float4 bo = *(const float4*)(wo1 + k);
            sWp1[(k + 0) * 8 + rp] = make_float2(be.x, bo.x);
            sWp1[(k + 1) * 8 + rp] = make_float2(be.y, bo.y);
            sWp1[(k + 2) * 8 + rp] = make_float2(be.z, bo.z);
            sWp1[(k + 3) * 8 + rp] = make_float2(be.w, bo.w);
            float4 ce = *(const float4*)(we2 + k);
            float4 co = *(const float4*)(wo2 + k);
            sWp1[(512 + k + 0) * 8 + rp] = make_float2(ce.x, co.x);
            sWp1[(512 + k + 1) * 8 + rp] = make_float2(ce.y, co.y);
            sWp1[(512 + k + 2) * 8 + rp] = make_float2(ce.z, co.z);
            sWp1[(512 + k + 3) * 8 + rp] = make_float2(ce.w, co.w);
        }
    }
    // ---- init: zero this CTA's h rows (both buffers), cell states, layer1 bias ----
    {
        #pragma unroll
        for (int i = 0; i < 4; ++i) {
            int e   = tid + i * 256;              // 0..1023
            int buf = e >> 9;
            int rem = e & 511;
            int r8  = rem >> 6;                   // 0..7
            int b   = rem & 63;
            int grow = (r8 < 4) ? (u0 + r8) : (512 + u0 + (r8 - 4));
            g_hall[((size_t)buf * 1024 + grow) * 64 + b] = 0.f;
        }
        sC0[tid] = 0.f;
        sC1[tid] = 0.f;
        if (tid < 16) {
            int q = tid >> 2, j = tid & 3;
            int col = q * 512 + u0 + j;
            sB1[tid] = bih1[col] + bhh1[col];
        }
    }
    grid_sync();

    const int ks = tid >> 5;                // warp = k-slice
    const int bp = tid & 31;                // batch pair (batches 2bp, 2bp+1)
    const int jj = tid >> 6, bb = tid & 63; // gate-phase mapping

    int cur = 0;
    for (int s = 0; s <= TT; ++s) {
        const bool doA = (s < TT);
        const bool doB = (s >= 1);

        float xv[4];
        if (doA) {
            #pragma unroll
            for (int q = 0; q < 4; ++q)
                xv[q] = __ldg(g_xw + ((size_t)s * GG + q * 512 + u0 + jj) * 64 + bb);
        }

        // ---- dot A: layer0, K=512 (h0 rows of hall[cur]) ----
        if (doA) {
            u64 a0[8], a1[8];
            #pragma unroll
            for (int i = 0; i < 8; ++i) { a0[i] = 0ull; a1[i] = 0ull; }
            const u64* hp = (const u64*)(g_hall + ((size_t)cur * 1024 + ks * 64) * 64) + bp;
            const ulonglong2* wq = (const ulonglong2*)(sWp0 + (ks * 64) * 8);
            #pragma unroll 8
            for (int kk = 0; kk < 64; ++kk) {
                u64 hraw = __ldcg(hp + (size_t)kk * 32);   // (h_b0, h_b1) plain
                float2 hv = unpack2(hraw);
                u64 hd0 = pack2(hv.x, hv.x);
                u64 hd1 = pack2(hv.y, hv.y);
                const ulonglong2* wk = wq + kk * 4;
                #pragma unroll
                for (int p = 0; p < 4; ++p) {
                    ulonglong2 w2 = wk[p];                 // rowpairs 2p, 2p+1
                    ffma2(a0[2 * p + 0], w2.x, hd0); ffma2(a1[2 * p + 0], w2.x, hd1);
                    ffma2(a0[2 * p + 1], w2.y, hd0); ffma2(a1[2 * p + 1], w2.y, hd1);
                }
            }
            #pragma unroll
            for (int rp = 0; rp < 8; ++rp)
                *(ulonglong2*)(sPA + ((ks * 8 + rp) * 64 + 2 * bp)) =
                    make_ulonglong2(a0[rp], a1[rp]);
        }
        // ---- dot B: layer1, K=1024 ([h0=y0 | h1] of hall[cur], fused weights) ----
        if (doB) {
            u64 a0[8], a1[8];
            #pragma unroll
            for (int i = 0; i < 8; ++i) { a0[i] = 0ull; a1[i] = 0ull; }
            const u64* hp = (const u64*)(g_hall + ((size_t)cur * 1024 + ks * 128) * 64) + bp;
            const ulonglong2* wq = (const ulonglong2*)(sWp1 + (ks * 128) * 8);
            #pragma unroll 8
            for (int kk = 0; kk < 128; ++kk) {
                u64 hraw = __ldcg(hp + (size_t)kk * 32);
                float2 hv = unpack2(hraw);
                u64 hd0 = pack2(hv.x, hv.x);
                u64 hd1 = pack2(hv.y, hv.y);
                const ulonglong2* wk = wq + kk * 4;
                #pragma unroll
                for (int p = 0; p < 4; ++p) {
                    ulonglong2 w2 = wk[p];
                    ffma2(a0[2 * p + 0], w2.x, hd0); ffma2(a1[2 * p + 0], w2.x, hd1);
                    ffma2(a0[2 * p + 1], w2.y, hd0); ffma2(a1[2 * p + 1], w2.y, hd1);
                }
            }
            #pragma unroll
            for (int rp = 0; rp < 8; ++rp)
                *(ulonglong2*)(sPB + ((ks * 8 + rp) * 64 + 2 * bp)) =
                    make_ulonglong2(a0[rp], a1[rp]);
        }
        __syncthreads();

        // ---- gates A: layer0, thread = (jj unit, bb batch) ----
        if (doA) {
            float g4[4];
            const float* pf = (const float*)sPA;
            #pragma unroll
            for (int q = 0; q < 4; ++q) {
                int rp = q * 2 + (jj >> 1);
                int rh = jj & 1;
                float v = xv[q];
                #pragma unroll
                for (int k2 = 0; k2 < 8; ++k2)
                    v += pf[(((k2 * 8 + rp) * 64) + bb) * 2 + rh];
                g4[q] = v;
            }
            float iv = 1.f / (1.f + __expf(-g4[0]));
            float fv = 1.f / (1.f + __expf(-g4[1]));
            float gv = tanhf(g4[2]);
            float ov = 1.f / (1.f + __expf(-g4[3]));
            float c = fv * sC0[jj * 64 + bb] + iv * gv;
            sC0[jj * 64 + bb] = c;
            float h = ov * tanhf(c);
            g_hall[((size_t)(cur ^ 1) * 1024 + u0 + jj) * 64 + bb] = h;
        }
        // ---- gates B: layer1 (t = s-1) ----
        if (doB) {
            float g4[4];
            const float* pf = (const float*)sPB;
            #pragma unroll
            for (int q = 0; q < 4; ++q) {
                int rp = q * 2 + (jj >> 1);
                int rh = jj & 1;
                float v = sB1[q * 4 + jj];
                #pragma unroll
                for (int k2 = 0; k2 < 8; ++k2)
                    v += pf[(((k2 * 8 + rp) * 64) + bb) * 2 + rh];
                g4[q] = v;
            }
            float iv = 1.f / (1.f + __expf(-g4[0]));
            float fv = 1.f / (1.f + __expf(-g4[1]));
            float gv = tanhf(g4[2]);
            float ov = 1.f / (1.f + __expf(-g4[3]));
            float c = fv * sC1[jj * 64 + bb] + iv * gv;
            sC1[jj * 64 + bb] = c;
            float h = ov * tanhf(c);
            g_hall[((size_t)(cur ^ 1) * 1024 + 512 + u0 + jj) * 64 + bb] = h;
            g_y1[((size_t)(s - 1) * HH + u0 + jj) * 64 + bb] = h;
        }
        grid_sync();
        cur ^= 1;
    }
}

// ---------------- output gather ----------------
__global__ void out_kernel(const int* __restrict__ sen_len, float* __restrict__ out) {
    int idx = blockIdx.x * blockDim.x + threadIdx.x;
    if (idx >= BB * HH) return;
    int b = idx >> 9;
    int u = idx & (HH - 1);
    int t = sen_len[b] - 1;
    out[idx] = g_y1[((size_t)t * HH + u) * BB + b];
}

// ---------------- launch ----------------
static const int REC_SMEM = (512 * 8 + 1024 * 8) * 8   // sWp0 + sWp1 (float2)
                          + 2 * (8 * 8 * 64) * 8       // sPA + sPB (u64)
                          + 2 * 256 * 4 + 16 * 4;      // sC0,sC1,sB1  = 165952

extern "C" void kernel_launch(void* const* d_in, const int* in_sizes, int n_in,
                              void* d_out, int out_size) {
    const int*   src     = (const int*)d_in[0];
    const int*   sen_len = (const int*)d_in[1];
    const float* emb     = (const float*)d_in[2];
    const float* Wih0    = (const float*)d_in[3];
    const float* Whh0    = (const float*)d_in[4];
    const float* bih0    = (const float*)d_in[5];
    const float* bhh0    = (const float*)d_in[6];
    const float* Wih1    = (const float*)d_in[7];
    const float* Whh1    = (const float*)d_in[8];
    const float* bih1    = (const float*)d_in[9];
    const float* bhh1    = (const float*)d_in[10];
    float* out = (float*)d_out;

    cudaFuncSetAttribute(lstm_fused_kernel,
                         cudaFuncAttributeMaxDynamicSharedMemorySize, REC_SMEM);

    embed_kernel<<<(TT * EE * BB + 255) / 256, 256>>>(src, emb);

    dim3 ggrid(GG / 128, TT);
    gemm_xw_kernel<<<ggrid, 128>>>(Wih0, bih0, bhh0);

    lstm_fused_kernel<<<NCTA, 256, REC_SMEM>>>(Whh0, Wih1, Whh1, bih1, bhh1);

    out_kernel<<<(BB * HH + 255) / 256, 256>>>(sen_len, out);
}

// round 11
// speedup vs baseline: 1.7061x; 1.0817x over previous
#include <cuda_runtime.h>
#include <math.h>

#define TT   512
#define BB   64
#define HH   512
#define GG   2048   // 4*HH
#define EE   512
#define NCTA 128

typedef unsigned long long u64;

// ---------------- packed fp32x2 helpers (sm_103a FFMA2) ----------------
__device__ __forceinline__ u64 pack2(float lo, float hi) {
    u64 r; asm("mov.b64 %0,{%1,%2};" : "=l"(r) : "f"(lo), "f"(hi)); return r;
}
__device__ __forceinline__ void ffma2(u64 &d, u64 a, u64 b) {
    asm("fma.rn.f32x2 %0,%1,%2,%0;" : "+l"(d) : "l"(a), "l"(b));
}
__device__ __forceinline__ float2 unpack2(u64 v) {
    float2 f; asm("mov.b64 {%0,%1},%2;" : "=f"(f.x), "=f"(f.y) : "l"(v)); return f;
}

// ---------------- scratch (device globals) ----------------
__device__ float g_x0[(size_t)TT * EE * BB];     // embedded input,  [T][E][B]
__device__ float g_xw[(size_t)TT * GG * BB];     // x@Wih0 + bias0,  [T][G][B]
__device__ float g_y1[(size_t)TT * HH * BB];     // layer1 outputs,  [T][H][B]
__device__ float g_hall[2 * 1024 * BB];          // [2 buf][h0:0-511 | h1:512-1023][B]
__device__ unsigned g_bar;                       // grid barrier counter

// ---------------- grid barrier (128 co-resident CTAs, wrap-safe) ----------------
__device__ __forceinline__ void grid_sync() {
    __syncthreads();
    if (threadIdx.x == 0) {
        __threadfence();
        unsigned ticket = atomicAdd(&g_bar, 1u);
        unsigned target = ticket - (ticket & (NCTA - 1)) + NCTA;
        while ((int)(*(volatile unsigned*)&g_bar - target) < 0) { }
        __threadfence();
    }
    __syncthreads();
}

// ---------------- embedding gather ----------------
__global__ void embed_kernel(const int* __restrict__ src,
                             const float* __restrict__ emb) {
    size_t idx = (size_t)blockIdx.x * blockDim.x + threadIdx.x;
    if (idx >= (size_t)TT * EE * BB) return;
    int b = (int)(idx & 63);
    int e = (int)((idx >> 6) & (EE - 1));
    int t = (int)(idx >> 15);
    g_x0[idx] = emb[(size_t)src[t * BB + b] * EE + e];
}

// ---------------- GEMM (R3 version): layer-0 xW only ----------------
__global__ void __launch_bounds__(128) gemm_xw_kernel(const float* __restrict__ W,
                                                      const float* __restrict__ b1,
                                                      const float* __restrict__ b2) {
    const float* __restrict__ A = g_x0;
    float* __restrict__ C = g_xw;

    __shared__ float As[16][64];     // [k][b]
    __shared__ float Ws[16][132];    // [k][col], padded

    const int tid = threadIdx.x;
    const int t   = blockIdx.y;
    const int n0  = blockIdx.x * 128;
    const int bx  = tid & 7;
    const int cy  = tid >> 3;
    const int b0  = bx * 8;
    const int c0  = cy * 8;
    const int lw_c = tid >> 2;
    const int lw_q = tid & 3;

    u64 acc[8][4];
    #pragma unroll
    for (int j = 0; j < 8; ++j)
        #pragma unroll
        for (int p = 0; p < 4; ++p) acc[j][p] = 0ull;

    for (int k0 = 0; k0 < 512; k0 += 16) {
        #pragma unroll
        for (int u = 0; u < 2; ++u) {
            int f  = tid * 2 + u;
            int kk = f >> 4, bb4 = (f & 15) * 4;
            *(float4*)&As[kk][bb4] =
                *(const float4*)(A + ((size_t)t * 512 + k0 + kk) * 64 + bb4);
        }
        #pragma unroll
        for (int cb = 0; cb < 4; ++cb) {
            int c = cb * 32 + lw_c;
            float4 w = *(const float4*)(W + (size_t)(n0 + c) * 512 + k0 + lw_q * 4);
            Ws[lw_q * 4 + 0][c] = w.x;
            Ws[lw_q * 4 + 1][c] = w.y;
            Ws[lw_q * 4 + 2][c] = w.z;
            Ws[lw_q * 4 + 3][c] = w.w;
        }
        __syncthreads();

        #pragma unroll
        for (int kk = 0; kk < 16; ++kk) {
            ulonglong2 a01 = *(const ulonglong2*)&As[kk][b0];
            ulonglong2 a23 = *(const ulonglong2*)&As[kk][b0 + 4];
            float4 wA = *(const float4*)&Ws[kk][c0];
            float4 wB = *(const float4*)&Ws[kk][c0 + 4];
            float wv[8] = {wA.x, wA.y, wA.z, wA.w, wB.x, wB.y, wB.z, wB.w};
            #pragma unroll
            for (int j = 0; j < 8; ++j) {
                u64 wp = pack2(wv[j], wv[j]);
                ffma2(acc[j][0], a01.x, wp);
                ffma2(acc[j][1], a01.y, wp);
                ffma2(acc[j][2], a23.x, wp);
                ffma2(acc[j][3], a23.y, wp);
            }
        }
        __syncthreads();
    }

    #pragma unroll
    for (int j = 0; j < 8; ++j) {
        int col = n0 + c0 + j;
        float bias = b1[col] + b2[col];
        float2 p0 = unpack2(acc[j][0]);
        float2 p1 = unpack2(acc[j][1]);
        float2 p2 = unpack2(acc[j][2]);
        float2 p3 = unpack2(acc[j][3]);
        float4 v0 = make_float4(p0.x + bias, p0.y + bias, p1.x + bias, p1.y + bias);
        float4 v1 = make_float4(p2.x + bias, p2.y + bias, p3.x + bias, p3.y + bias);
        float* cp = C + ((size_t)t * GG + col) * BB + b0;
        *(float4*)cp       = v0;
        *(float4*)(cp + 4) = v1;
    }
}

// ---------------- fused 2-layer persistent LSTM recurrence ----------------
// Step s: layer0 @ t=s and layer1 @ t=s-1. The h0 pass feeds BOTH Whh0 (layer0)
// and Wih1 (layer1 input half) -- h0 read once per step instead of twice.
__global__ void __launch_bounds__(256, 1) lstm_fused_kernel(
        const float* __restrict__ Whh0,
        const float* __restrict__ Wih1,
        const float* __restrict__ Whh1,
        const float* __restrict__ bih1,
        const float* __restrict__ bhh1) {
    extern __shared__ float smem[];
    float2* sWp0 = (float2*)smem;                 // [512 k][8 rp]  Whh0 (32 KB)
    float2* sWp1 = sWp0 + 512 * 8;                // [1024 k][8 rp] Wih1|Whh1 (64 KB)
    u64*    sPA  = (u64*)(sWp1 + 1024 * 8);       // [8 ks][8 rp][64 b] (32 KB)
    u64*    sPB  = sPA + 8 * 8 * 64;              // same (32 KB)
    float*  sC0  = (float*)(sPB + 8 * 8 * 64);    // [4][64]
    float*  sC1  = sC0 + 256;                     // [4][64]
    float*  sB1  = sC1 + 256;                     // [16]

    const int tid = threadIdx.x;
    const int cta = blockIdx.x;
    const int u0  = cta * 4;

    // ---- weight fills: sWp[k][rp] = (W[row_e][k], W[row_o][k]), rp = q*2+jh ----
    {
        const int rp = tid >> 5;              // 0..7
        const int ln = tid & 31;
        const int q = rp >> 1, jh = rp & 1;
        const int re = q * 512 + u0 + 2 * jh;
        const float* we0 = Whh0 + (size_t)re * 512;
        const float* wo0 = we0 + 512;
        const float* we1 = Wih1 + (size_t)re * 512;
        const float* wo1 = we1 + 512;
        const float* we2 = Whh1 + (size_t)re * 512;
        const float* wo2 = we2 + 512;
        #pragma unroll
        for (int i = 0; i < 4; ++i) {
            int k = ln * 16 + i * 4;
            float4 ae = *(const float4*)(we0 + k);
            float4 ao = *(const float4*)(wo0 + k);
            sWp0[(k + 0) * 8 + rp] = make_float2(ae.x, ao.x);
            sWp0[(k + 1) * 8 + rp] = make_float2(ae.y, ao.y);
            sWp0[(k + 2) * 8 + rp] = make_float2(ae.z, ao.z);
            sWp0[(k + 3) * 8 + rp] = make_float2(ae.w, ao.w);
            float4 be = *(const float4*)(we1 + k);
            float4 bo = *(const float4*)(wo1 + k);
            sWp1[(k + 0) * 8 + rp] = make_float2(be.x, bo.x);
            sWp1[(k + 1) * 8 + rp] = make_float2(be.y, bo.y);
            sWp1[(k + 2) * 8 + rp] = make_float2(be.z, bo.z);
            sWp1[(k + 3) * 8 + rp] = make_float2(be.w, bo.w);
            float4 ce = *(const float4*)(we2 + k);
            float4 co = *(const float4*)(wo2 + k);
            sWp1[(512 + k + 0) * 8 + rp] = make_float2(ce.x, co.x);
            sWp1[(512 + k + 1) * 8 + rp] = make_float2(ce.y, co.y);
            sWp1[(512 + k + 2) * 8 + rp] = make_float2(ce.z, co.z);
            sWp1[(512 + k + 3) * 8 + rp] = make_float2(ce.w, co.w);
        }
    }
    // ---- init ----
    {
        #pragma unroll
        for (int i = 0; i < 4; ++i) {
            int e   = tid + i * 256;
            int buf = e >> 9;
            int rem = e & 511;
            int r8  = rem >> 6;
            int b   = rem & 63;
            int grow = (r8 < 4) ? (u0 + r8) : (512 + u0 + (r8 - 4));
            g_hall[((size_t)buf * 1024 + grow) * 64 + b] = 0.f;
        }
        sC0[tid] = 0.f;
        sC1[tid] = 0.f;
        if (tid < 16) {
            int q = tid >> 2, j = tid & 3;
            int col = q * 512 + u0 + j;
            sB1[tid] = bih1[col] + bhh1[col];
        }
    }
    grid_sync();

    const int ks = tid >> 5;                // warp = k-slice
    const int bp = tid & 31;                // batch pair (batches 2bp, 2bp+1)
    const int jj = tid >> 6, bb = tid & 63; // gate-phase mapping

    int cur = 0;
    for (int s = 0; s <= TT; ++s) {
        const bool doA = (s < TT);
        const bool doB = (s >= 1);
        const int  sx  = doA ? s : (TT - 1);   // clamped (values unused when !doA)

        float xv[4];
        #pragma unroll
        for (int q = 0; q < 4; ++q)
            xv[q] = __ldg(g_xw + ((size_t)sx * GG + q * 512 + u0 + jj) * 64 + bb);

        // ---- pass 1 over h0[cur]: feeds accA (Whh0) and accB (Wih1) ----
        u64 aA0[8], aA1[8], aB0[8], aB1[8];
        #pragma unroll
        for (int i = 0; i < 8; ++i) { aA0[i] = 0ull; aA1[i] = 0ull; aB0[i] = 0ull; aB1[i] = 0ull; }
        {
            const u64* hp = (const u64*)(g_hall + ((size_t)cur * 1024 + ks * 64) * 64) + bp;
            const ulonglong2* wq0 = (const ulonglong2*)(sWp0 + (ks * 64) * 8);
            const ulonglong2* wq1 = (const ulonglong2*)(sWp1 + (ks * 64) * 8);
            #pragma unroll 8
            for (int kk = 0; kk < 64; ++kk) {
                u64 hraw = __ldcg(hp + (size_t)kk * 32);
                float2 hv = unpack2(hraw);
                u64 hd0 = pack2(hv.x, hv.x);
                u64 hd1 = pack2(hv.y, hv.y);
                const ulonglong2* wk0 = wq0 + kk * 4;
                const ulonglong2* wk1 = wq1 + kk * 4;
                #pragma unroll
                for (int p = 0; p < 4; ++p) {
                    ulonglong2 w2 = wk0[p];
                    ffma2(aA0[2 * p + 0], w2.x, hd0); ffma2(aA1[2 * p + 0], w2.x, hd1);
                    ffma2(aA0[2 * p + 1], w2.y, hd0); ffma2(aA1[2 * p + 1], w2.y, hd1);
                    ulonglong2 v2 = wk1[p];
                    ffma2(aB0[2 * p + 0], v2.x, hd0); ffma2(aB1[2 * p + 0], v2.x, hd1);
                    ffma2(aB0[2 * p + 1], v2.y, hd0); ffma2(aB1[2 * p + 1], v2.y, hd1);
                }
            }
        }
        // ---- pass 2 over h1[cur]: accB += Whh1 ----
        {
            const u64* hp = (const u64*)(g_hall + ((size_t)cur * 1024 + 512 + ks * 64) * 64) + bp;
            const ulonglong2* wq2 = (const ulonglong2*)(sWp1 + (512 + ks * 64) * 8);
            #pragma unroll 8
            for (int kk = 0; kk < 64; ++kk) {
                u64 hraw = __ldcg(hp + (size_t)kk * 32);
                float2 hv = unpack2(hraw);
                u64 hd0 = pack2(hv.x, hv.x);
                u64 hd1 = pack2(hv.y, hv.y);
                const ulonglong2* wk = wq2 + kk * 4;
                #pragma unroll
                for (int p = 0; p < 4; ++p) {
                    ulonglong2 w2 = wk[p];
                    ffma2(aB0[2 * p + 0], w2.x, hd0); ffma2(aB1[2 * p + 0], w2.x, hd1);
                    ffma2(aB0[2 * p + 1], w2.y, hd0); ffma2(aB1[2 * p + 1], w2.y, hd1);
                }
            }
        }
        #pragma unroll
        for (int rp = 0; rp < 8; ++rp) {
            *(ulonglong2*)(sPA + ((ks * 8 + rp) * 64 + 2 * bp)) = make_ulonglong2(aA0[rp], aA1[rp]);
            *(ulonglong2*)(sPB + ((ks * 8 + rp) * 64 + 2 * bp)) = make_ulonglong2(aB0[rp], aB1[rp]);
        }
        __syncthreads();

        // ---- gates A: layer0 @ t=s ----
        if (doA) {
            float g4[4];
            const float* pf = (const float*)sPA;
            #pragma unroll
            for (int q = 0; q < 4; ++q) {
                int rp = q * 2 + (jj >> 1);
                int rh = jj & 1;
                float v = xv[q];
                #pragma unroll
                for (int k2 = 0; k2 < 8; ++k2)
                    v += pf[(((k2 * 8 + rp) * 64) + bb) * 2 + rh];
                g4[q] = v;
            }
            float iv = 1.f / (1.f + __expf(-g4[0]));
            float fv = 1.f / (1.f + __expf(-g4[1]));
            float gv = tanhf(g4[2]);
            float ov = 1.f / (1.f + __expf(-g4[3]));
            float c = fv * sC0[jj * 64 + bb] + iv * gv;
            sC0[jj * 64 + bb] = c;
            float h = ov * tanhf(c);
            g_hall[((size_t)(cur ^ 1) * 1024 + u0 + jj) * 64 + bb] = h;
        }
        // ---- gates B: layer1 @ t=s-1 ----
        if (doB) {
            float g4[4];
            const float* pf = (const float*)sPB;
            #pragma unroll
            for (int q = 0; q < 4; ++q) {
                int rp = q * 2 + (jj >> 1);
                int rh = jj & 1;
                float v = sB1[q * 4 + jj];
                #pragma unroll
                for (int k2 = 0; k2 < 8; ++k2)
                    v += pf[(((k2 * 8 + rp) * 64) + bb) * 2 + rh];
                g4[q] = v;
            }
            float iv = 1.f / (1.f + __expf(-g4[0]));
            float fv = 1.f / (1.f + __expf(-g4[1]));
            float gv = tanhf(g4[2]);
            float ov = 1.f / (1.f + __expf(-g4[3]));
            float c = fv * sC1[jj * 64 + bb] + iv * gv;
            sC1[jj * 64 + bb] = c;
            float h = ov * tanhf(c);
            g_hall[((size_t)(cur ^ 1) * 1024 + 512 + u0 + jj) * 64 + bb] = h;
            g_y1[((size_t)(s - 1) * HH + u0 + jj) * 64 + bb] = h;
        }
        grid_sync();
        cur ^= 1;
    }
}

// ---------------- output gather ----------------
__global__ void out_kernel(const int* __restrict__ sen_len, float* __restrict__ out) {
    int idx = blockIdx.x * blockDim.x + threadIdx.x;
    if (idx >= BB * HH) return;
    int b = idx >> 9;
    int u = idx & (HH - 1);
    int t = sen_len[b] - 1;
    out[idx] = g_y1[((size_t)t * HH + u) * BB + b];
}

// ---------------- launch ----------------
static const int REC_SMEM = (512 * 8 + 1024 * 8) * 8   // sWp0 + sWp1 (float2)
                          + 2 * (8 * 8 * 64) * 8       // sPA + sPB (u64)
                          + 2 * 256 * 4 + 16 * 4;      // sC0,sC1,sB1  = 165952

extern "C" void kernel_launch(void* const* d_in, const int* in_sizes, int n_in,
                              void* d_out, int out_size) {
    const int*   src     = (const int*)d_in[0];
    const int*   sen_len = (const int*)d_in[1];
    const float* emb     = (const float*)d_in[2];
    const float* Wih0    = (const float*)d_in[3];
    const float* Whh0    = (const float*)d_in[4];
    const float* bih0    = (const float*)d_in[5];
    const float* bhh0    = (const float*)d_in[6];
    const float* Wih1    = (const float*)d_in[7];
    const float* Whh1    = (const float*)d_in[8];
    const float* bih1    = (const float*)d_in[9];
    const float* bhh1    = (const float*)d_in[10];
    float* out = (float*)d_out;

    cudaFuncSetAttribute(lstm_fused_kernel,
                         cudaFuncAttributeMaxDynamicSharedMemorySize, REC_SMEM);

    embed_kernel<<<(TT * EE * BB + 255) / 256, 256>>>(src, emb);

    dim3 ggrid(GG / 128, TT);
    gemm_xw_kernel<<<ggrid, 128>>>(Wih0, bih0, bhh0);

    lstm_fused_kernel<<<NCTA, 256, REC_SMEM>>>(Whh0, Wih1, Whh1, bih1, bhh1);

    out_kernel<<<(BB * HH + 255) / 256, 256>>>(sen_len, out);
}